// round 1
// baseline (speedup 1.0000x reference)
#include <cuda_runtime.h>

// Problem constants (fixed shapes from reference):
//   x: (B=8, ns=4, D=512, nc=64) fp32
//   out: concat(map_hidden, map_mask), each (B, D, 4, nc=64, nc+1=65) fp32
// For rel in 0..3, base = 1<<rel:
//   out_hidden[b,d,rel,i,j] = max(x[b,rel,d, i .. i + (j-i)/base - 1])
//   whenever i % base == 0, (j-i) % base == 0, j > i, j < 64; else 0.
//   out_mask = 1.0 at same positions, else 0.

#define B_DIM 8
#define D_DIM 512
#define NC 64
#define NJ 65
#define REGION (4 * NC * NJ)   // 16640 floats per (b,d) per half
#define SROWS 120              // 64 + 32 + 16 + 8 running-max rows

__global__ __launch_bounds__(256, 1)
void prop3d_kernel(const float* __restrict__ x, float* __restrict__ out,
                   long half_elems) {
    __shared__ float xs[4][NC];        // input slice
    __shared__ float S[SROWS][NC];     // S[row][e] = max(x[i(row) .. e])

    const int bd = blockIdx.x;          // b*512 + d
    const int b  = bd >> 9;
    const int d  = bd & 511;
    const int tid = threadIdx.x;

    // ---- load x[b, rel, d, :] for rel = 0..3 (coalesced 256B per rel) ----
    {
        int rel = tid >> 6;
        int c   = tid & 63;
        xs[rel][c] = x[((((b << 2) + rel) * D_DIM) + d) * NC + c];
    }
    __syncthreads();

    // ---- build running-max rows: only i that are multiples of base ----
    // row layout: rel0 rows 0..63 (i=r), rel1 rows 64..95 (i=2(r-64)),
    //             rel2 rows 96..111 (i=4(r-96)), rel3 rows 112..119 (i=8(r-112))
    if (tid < SROWS) {
        int rel, i;
        if (tid < 64)       { rel = 0; i = tid; }
        else if (tid < 96)  { rel = 1; i = (tid - 64) << 1; }
        else if (tid < 112) { rel = 2; i = (tid - 96) << 2; }
        else                { rel = 3; i = (tid - 112) << 3; }
        float m = xs[rel][i];
        S[tid][i] = m;
        for (int e = i + 1; e < NC; e++) {
            m = fmaxf(m, xs[rel][e]);
            S[tid][e] = m;
        }
    }
    __syncthreads();

    // ---- write loop: 4160 float4 chunks cover the 16640-float region ----
    float* __restrict__ hid = out + (long)bd * REGION;
    float* __restrict__ msk = hid + half_elems;

    for (int q = tid; q < REGION / 4; q += 256) {
        int rel = q / 1040;                 // 1040 float4 per rel block
        int er  = (q - rel * 1040) << 2;    // element offset within rel block
        int i   = er / 65;
        int j   = er - i * 65;
        int base_m1 = (1 << rel) - 1;
        int rowb    = 128 - (128 >> rel);   // 0, 64, 96, 112

        float4 h, m;
        float* hp = reinterpret_cast<float*>(&h);
        float* mp = reinterpret_cast<float*>(&m);

        #pragma unroll
        for (int l = 0; l < 4; l++) {
            int jj = j + l;
            int ii = i;
            if (jj >= NJ) { jj -= NJ; ii += 1; }   // at most one row wrap
            bool hit = (jj > ii) & (jj < NC) &
                       ((ii & base_m1) == 0) & (((jj - ii) & base_m1) == 0);
            float hv = 0.0f, mv = 0.0f;
            if (hit) {
                int k = (jj - ii) >> rel;          // window length in elements
                hv = S[rowb + (ii >> rel)][ii + k - 1];
                mv = 1.0f;
            }
            hp[l] = hv;
            mp[l] = mv;
        }

        int off = q << 2;                          // == rel*4160 + er
        *reinterpret_cast<float4*>(hid + off) = h;
        *reinterpret_cast<float4*>(msk + off) = m;
    }
}

extern "C" void kernel_launch(void* const* d_in, const int* in_sizes, int n_in,
                              void* d_out, int out_size) {
    const float* x = (const float*)d_in[0];
    float* out = (float*)d_out;
    long half = (long)out_size / 2;   // map_hidden elements; map_mask follows

    dim3 grid(B_DIM * D_DIM);         // 4096 CTAs, one per (b,d)
    dim3 block(256);
    prop3d_kernel<<<grid, block>>>(x, out, half);
}